// round 4
// baseline (speedup 1.0000x reference)
#include <cuda_runtime.h>
#include <stdint.h>
#include <math.h>

// ===== RNG variant switch ===================================================
// 1 = jax_threefry_partitionable=True (modern JAX default):
//       step key  = threefry2x32(base_key, (0, t))          -> (o0, o1)
//       bits[idx] = o0 ^ o1 of threefry2x32(step_key, (0, idx))
// 0 = legacy threefry semantics (iota halving for split and bits)
#define JAX_PARTITIONABLE 1
// ============================================================================

#define NROWS   65536
#define TSTEPS  12
#define WPB     8          // warps per block
#define THREADS 256
#define NBLOCKS 296        // 2 per SM on 148-SM sm_100a

// output layout (float32): seq | ent | logp | cnt | lengths | mask
#define OFF_ENT  (NROWS * TSTEPS)
#define OFF_LP   (2 * NROWS * TSTEPS)
#define OFF_CNT  (3 * NROWS * TSTEPS)
#define OFF_LEN  (OFF_CNT + NROWS)
#define OFF_MASK (OFF_LEN + NROWS)

// shared layout in float (4B) slots
#define SM_WH    0          // 128x128           = 16384
#define SM_WX    16384      // 32x128            =  4096
#define SM_WP    20480      // 128x16            =  2048
#define SM_B     22528      // 128
#define SM_BP    22656      // 16
#define SM_IN0   22672      // 32
#define SM_H0    22704      // 128
#define SM_KEY   22832      // 24 u32 (12 step keys)
#define SM_HS    22856      // WPB * 4 rows * 128  = 4096
#define SM_SEQ   26952      // WPB * 4 * 12 (int)  = 384
#define SM_ST    27336      // WPB * 4 * 8  (int)  = 256
#define SM_TOTF  27592      // 110368 bytes

__device__ __forceinline__ uint32_t rotl32(uint32_t x, int n) {
    return (x << n) | (x >> (32 - n));
}

// Threefry-2x32, 20 rounds (exact JAX cipher)
__device__ __forceinline__ void tf2x32(uint32_t k0, uint32_t k1,
                                       uint32_t &x0, uint32_t &x1) {
    uint32_t k2 = k0 ^ k1 ^ 0x1BD11BDAu;
    x0 += k0; x1 += k1;
#define TFR(r) { x0 += x1; x1 = rotl32(x1, (r)); x1 ^= x0; }
    TFR(13) TFR(15) TFR(26) TFR(6)
    x0 += k1; x1 += k2 + 1u;
    TFR(17) TFR(29) TFR(16) TFR(24)
    x0 += k2; x1 += k0 + 2u;
    TFR(13) TFR(15) TFR(26) TFR(6)
    x0 += k0; x1 += k1 + 3u;
    TFR(17) TFR(29) TFR(16) TFR(24)
    x0 += k1; x1 += k2 + 4u;
    TFR(13) TFR(15) TFR(26) TFR(6)
    x0 += k2; x1 += k0 + 5u;
#undef TFR
}

// one uniform u32 for flat element index idx of a (NROWS,16) draw
__device__ __forceinline__ uint32_t gbits(uint32_t k0, uint32_t k1, uint32_t idx) {
#if JAX_PARTITIONABLE
    uint32_t a = 0u, b = idx;
    tf2x32(k0, k1, a, b);
    return a ^ b;
#else
    const uint32_t half = (uint32_t)(NROWS * 16) / 2u;  // 524288
    if (idx < half) {
        uint32_t a = idx, b = idx + half;
        tf2x32(k0, k1, a, b);
        return a;
    } else {
        uint32_t a = idx - half, b = idx;
        tf2x32(k0, k1, a, b);
        return b;
    }
#endif
}

__global__ void __launch_bounds__(THREADS, 2)
eq_sampler(const float* __restrict__ in0, const float* __restrict__ h0,
           const float* __restrict__ Wx, const float* __restrict__ Wh,
           const float* __restrict__ b,  const float* __restrict__ Wp,
           const float* __restrict__ bp, float* __restrict__ out) {
    extern __shared__ float sm[];
    int* smi = (int*)sm;
    const int tid = threadIdx.x;

    for (int i = tid; i < 16384; i += THREADS) sm[SM_WH + i] = Wh[i];
    for (int i = tid; i < 4096;  i += THREADS) sm[SM_WX + i] = Wx[i];
    for (int i = tid; i < 2048;  i += THREADS) sm[SM_WP + i] = Wp[i];
    if (tid < 128) sm[SM_B  + tid] = b[tid];
    if (tid < 16)  sm[SM_BP + tid] = bp[tid];
    if (tid < 32)  sm[SM_IN0 + tid] = in0[tid];
    if (tid < 128) sm[SM_H0 + tid] = h0[tid];

    if (tid == 0) {
        uint32_t* kp = (uint32_t*)(sm + SM_KEY);
        // base key = jax.random.key(42) -> (hi=0, lo=42); split into 12 step keys
#if JAX_PARTITIONABLE
        for (int t = 0; t < TSTEPS; t++) {
            uint32_t a = 0u, bb = (uint32_t)t;
            tf2x32(0u, 42u, a, bb);
            kp[2 * t] = a; kp[2 * t + 1] = bb;
        }
#else
        // legacy split: counts = iota(24); halves (0..11),(12..23); out = [o0[0..11], o1[0..11]]
        uint32_t ov[24];
        for (int j = 0; j < 12; j++) {
            uint32_t a = (uint32_t)j, bb = (uint32_t)(j + 12);
            tf2x32(0u, 42u, a, bb);
            ov[j] = a; ov[12 + j] = bb;
        }
        for (int t = 0; t < TSTEPS; t++) { kp[2 * t] = ov[2 * t]; kp[2 * t + 1] = ov[2 * t + 1]; }
#endif
    }
    __syncthreads();

    const int wid  = tid >> 5;
    const int lane = tid & 31;
    const float NEG_INF = __int_as_float(0xff800000);

    float* hbase = sm + SM_HS + wid * 512;           // 4 rows x 128
    float4* hb4  = (float4*)hbase;
    int* seqw = smi + SM_SEQ + wid * 48;             // 4 rows x 12
    int* stw  = smi + SM_ST  + wid * 32;             // 4 rows x {cnt,ln,act,hasvar,len,ps0,ps1,pad}

    // lane's token / row-pair assignment for the 16-wide phases
    const int g  = lane >> 4;        // half-warp group: 0 or 1
    const int tk = lane & 15;        // token id this lane evaluates
    const int rA = g;                // rows handled by this group
    const int rB = g + 2;

    // t=0 input projection (identical for every row): xw0[v] = sum_k in0[k]*Wx[k][lane*4+v]
    float xw0[4];
#pragma unroll
    for (int v = 0; v < 4; v++) {
        float s = 0.0f;
#pragma unroll
        for (int k = 0; k < 32; k++)
            s = fmaf(sm[SM_IN0 + k], sm[SM_WX + k * 128 + lane * 4 + v], s);
        xw0[v] = s;
    }
    float bvec[4];
    *(float4*)bvec = ((const float4*)(sm + SM_B))[lane];
    const float4 hinit = ((const float4*)(sm + SM_H0))[lane];

    const int totalWarps = gridDim.x * WPB;
    for (int grp = blockIdx.x * WPB + wid; grp < NROWS / 4; grp += totalWarps) {
        const int rowBase = grp * 4;

        // ---- init group state ----
#pragma unroll
        for (int r = 0; r < 4; r++) hb4[r * 32 + lane] = hinit;
        if (lane < 4) {
            int* st = stw + lane * 8;
            st[0] = 1;  // cnt
            st[1] = 0;  // ln
            st[2] = 1;  // act
            st[3] = 0;  // hasvar
            st[4] = 1;  // len (mask col 0)
            st[5] = -1; // ps0
            st[6] = -1; // ps1
            out[OFF_MASK + (size_t)(rowBase + lane) * 13] = 1.0f;
        }
        __syncwarp();

        for (int t = 0; t < TSTEPS; t++) {
            const uint32_t k0 = ((uint32_t*)(sm + SM_KEY))[2 * t];
            const uint32_t k1 = ((uint32_t*)(sm + SM_KEY))[2 * t + 1];

            // ---- x @ Wx (one-hot gather for t>0) ----
            float xw[4][4];
            if (t == 0) {
#pragma unroll
                for (int r = 0; r < 4; r++) {
                    xw[r][0] = xw0[0]; xw[r][1] = xw0[1];
                    xw[r][2] = xw0[2]; xw[r][3] = xw0[3];
                }
            } else {
#pragma unroll
                for (int r = 0; r < 4; r++) {
                    int p0 = stw[r * 8 + 5];
                    int p1 = stw[r * 8 + 6];
                    float4 a = make_float4(0.f, 0.f, 0.f, 0.f);
                    float4 c = make_float4(0.f, 0.f, 0.f, 0.f);
                    if (p0 >= 0) a = ((const float4*)(sm + SM_WX))[p0 * 32 + lane];
                    if (p1 >= 0) c = ((const float4*)(sm + SM_WX))[(16 + p1) * 32 + lane];
                    xw[r][0] = a.x + c.x; xw[r][1] = a.y + c.y;
                    xw[r][2] = a.z + c.z; xw[r][3] = a.w + c.w;
                }
            }

            // ---- h @ Wh : 4 rows, 4 outputs per lane ----
            float acc[4][4];
#pragma unroll
            for (int r = 0; r < 4; r++) {
                acc[r][0] = 0.f; acc[r][1] = 0.f; acc[r][2] = 0.f; acc[r][3] = 0.f;
            }
            const float4* Wh4 = (const float4*)sm;  // SM_WH == 0
#pragma unroll 4
            for (int k4 = 0; k4 < 32; k4++) {
                float h0a[4], h1a[4], h2a[4], h3a[4];
                *(float4*)h0a = hb4[k4];
                *(float4*)h1a = hb4[32 + k4];
                *(float4*)h2a = hb4[64 + k4];
                *(float4*)h3a = hb4[96 + k4];
#pragma unroll
                for (int kk = 0; kk < 4; kk++) {
                    float4 w = Wh4[(k4 * 4 + kk) * 32 + lane];
                    acc[0][0] = fmaf(h0a[kk], w.x, acc[0][0]);
                    acc[0][1] = fmaf(h0a[kk], w.y, acc[0][1]);
                    acc[0][2] = fmaf(h0a[kk], w.z, acc[0][2]);
                    acc[0][3] = fmaf(h0a[kk], w.w, acc[0][3]);
                    acc[1][0] = fmaf(h1a[kk], w.x, acc[1][0]);
                    acc[1][1] = fmaf(h1a[kk], w.y, acc[1][1]);
                    acc[1][2] = fmaf(h1a[kk], w.z, acc[1][2]);
                    acc[1][3] = fmaf(h1a[kk], w.w, acc[1][3]);
                    acc[2][0] = fmaf(h2a[kk], w.x, acc[2][0]);
                    acc[2][1] = fmaf(h2a[kk], w.y, acc[2][1]);
                    acc[2][2] = fmaf(h2a[kk], w.z, acc[2][2]);
                    acc[2][3] = fmaf(h2a[kk], w.w, acc[2][3]);
                    acc[3][0] = fmaf(h3a[kk], w.x, acc[3][0]);
                    acc[3][1] = fmaf(h3a[kk], w.y, acc[3][1]);
                    acc[3][2] = fmaf(h3a[kk], w.z, acc[3][2]);
                    acc[3][3] = fmaf(h3a[kk], w.w, acc[3][3]);
                }
            }
            __syncwarp();
            // h_new = tanh((x@Wx + h@Wh) + b)
#pragma unroll
            for (int r = 0; r < 4; r++) {
                float4 hn;
                hn.x = tanhf((xw[r][0] + acc[r][0]) + bvec[0]);
                hn.y = tanhf((xw[r][1] + acc[r][1]) + bvec[1]);
                hn.z = tanhf((xw[r][2] + acc[r][2]) + bvec[2]);
                hn.w = tanhf((xw[r][3] + acc[r][3]) + bvec[3]);
                hb4[r * 32 + lane] = hn;
            }
            __syncwarp();

            // ---- logits: lane evaluates token tk for rows rA and rB ----
            const float4* hA4 = (const float4*)(hbase + rA * 128);
            const float4* hB4 = (const float4*)(hbase + rB * 128);
            float accA = 0.f, accB = 0.f;
#pragma unroll 4
            for (int k4 = 0; k4 < 32; k4++) {
                float ha[4], hc[4];
                *(float4*)ha = hA4[k4];
                *(float4*)hc = hB4[k4];
#pragma unroll
                for (int kk = 0; kk < 4; kk++) {
                    float wp = sm[SM_WP + (k4 * 4 + kk) * 16 + tk];
                    accA = fmaf(ha[kk], wp, accA);
                    accB = fmaf(hc[kk], wp, accB);
                }
            }
            float lA = accA + sm[SM_BP + tk];
            float lB = accB + sm[SM_BP + tk];

            // ---- constraints (use PRE-update state) ----
            int cntA = stw[rA * 8 + 0], lnA = stw[rA * 8 + 1], hvA = stw[rA * 8 + 3];
            int cntB = stw[rB * 8 + 0], lnB = stw[rB * 8 + 1], hvB = stw[rB * 8 + 3];
            int clA = cntA + lnA, clB = cntB + lnB;
            bool okA = true, okB = true;
            if (tk >= 8 && clA < 2) okA = false;
            if (tk <  8 && clA > TSTEPS - 2) okA = false;
            if (tk == 8 && cntA == 1 && hvA == 0) okA = false;
            if (tk >= 8 && clB < 2) okB = false;
            if (tk <  8 && clB > TSTEPS - 2) okB = false;
            if (tk == 8 && cntB == 1 && hvB == 0) okB = false;

            // ---- exact two-stage softmax + mask + renorm (16-lane group ops) ----
            float mA = lA, mB = lB;
#pragma unroll
            for (int d = 1; d < 16; d <<= 1) {
                mA = fmaxf(mA, __shfl_xor_sync(0xffffffffu, mA, d));
                mB = fmaxf(mB, __shfl_xor_sync(0xffffffffu, mB, d));
            }
            float eA = expf(lA - mA), eB = expf(lB - mB);
            float zA = eA, zB = eB;
#pragma unroll
            for (int d = 1; d < 16; d <<= 1) {
                zA += __shfl_xor_sync(0xffffffffu, zA, d);
                zB += __shfl_xor_sync(0xffffffffu, zB, d);
            }
            float prA = eA / zA, prB = eB / zB;
            float pmA = okA ? prA : 0.0f;
            float pmB = okB ? prB : 0.0f;
            float sA = pmA, sB = pmB;
#pragma unroll
            for (int d = 1; d < 16; d <<= 1) {
                sA += __shfl_xor_sync(0xffffffffu, sA, d);
                sB += __shfl_xor_sync(0xffffffffu, sB, d);
            }
            float pA = pmA / sA, pB = pmB / sB;
            bool posA = pA > 0.0f, posB = pB > 0.0f;
            float logpA = posA ? logf(pA) : NEG_INF;
            float logpB = posB ? logf(pB) : NEG_INF;

            // ---- gumbel noise (exact threefry bits) ----
            uint32_t idxA = ((uint32_t)(rowBase + rA)) * 16u + (uint32_t)tk;
            uint32_t idxB = ((uint32_t)(rowBase + rB)) * 16u + (uint32_t)tk;
            uint32_t bA = gbits(k0, k1, idxA);
            uint32_t bB = gbits(k0, k1, idxB);
            float fA = __uint_as_float((bA >> 9) | 0x3f800000u) - 1.0f;
            float fB = __uint_as_float((bB >> 9) | 0x3f800000u) - 1.0f;
            float uA = (fA == 0.0f) ? 1.17549435e-38f : fA;
            float uB = (fB == 0.0f) ? 1.17549435e-38f : fB;
            float guA = -logf(-logf(uA));
            float guB = -logf(-logf(uB));
            float scA = posA ? (logpA + guA) : NEG_INF;
            float scB = posB ? (logpB + guB) : NEG_INF;

            // ---- argmax over 16 tokens (first-index tie-break) ----
            float bsA = scA, bsB = scB;
            int biA = tk, biB = tk;
#pragma unroll
            for (int d = 1; d < 16; d <<= 1) {
                float osA = __shfl_xor_sync(0xffffffffu, bsA, d);
                int   oiA = __shfl_xor_sync(0xffffffffu, biA, d);
                if (osA > bsA || (osA == bsA && oiA < biA)) { bsA = osA; biA = oiA; }
                float osB = __shfl_xor_sync(0xffffffffu, bsB, d);
                int   oiB = __shfl_xor_sync(0xffffffffu, biB, d);
                if (osB > bsB || (osB == bsB && oiB < biB)) { bsB = osB; biB = oiB; }
            }

            // ---- entropy ----
            float etA = posA ? pA * logpA : 0.0f;
            float etB = posB ? pB * logpB : 0.0f;
#pragma unroll
            for (int d = 1; d < 16; d <<= 1) {
                etA += __shfl_xor_sync(0xffffffffu, etA, d);
                etB += __shfl_xor_sync(0xffffffffu, etB, d);
            }
            float entA = -etA, entB = -etB;

            // ---- logp at sampled token ----
            float lpA = __shfl_sync(0xffffffffu, logpA, (lane & 16) + biA);
            float lpB = __shfl_sync(0xffffffffu, logpB, (lane & 16) + biB);

            // ---- writer lanes (0 and 16): state update + parent/sibling ----
            if (tk == 0) {
#pragma unroll
                for (int half = 0; half < 2; half++) {
                    int r    = half ? rB : rA;
                    int tok  = half ? biB : biA;
                    float lp = half ? lpB : lpA;
                    float en = half ? entB : entA;
                    int* st = stw + r * 8;
                    int row = rowBase + r;

                    seqw[r * 12 + t] = tok;
                    int ar  = (tok < 4) ? 2 : ((tok < 8) ? 1 : 0);
                    int cnt = st[0] - 1 + ar;
                    int ln  = st[1] + 1;
                    int act = (cnt > 0) && st[2];
                    st[0] = cnt; st[1] = ln; st[2] = act;
                    st[3] = st[3] | (tok >= 9);
                    st[4] += act;

                    out[(size_t)row * 12 + t]            = (float)tok;
                    out[OFF_ENT + (size_t)row * 12 + t]  = en;
                    out[OFF_LP  + (size_t)row * 12 + t]  = lp;
                    out[OFF_MASK + (size_t)row * 13 + 1 + t] = act ? 1.0f : 0.0f;

                    int ps0, ps1;
                    if (tok < 8) {
                        ps0 = tok; ps1 = -1;
                    } else {
                        ps0 = -1; ps1 = -1;
                        int c = 0;
                        bool found = false;
                        for (int i = t; i >= 0; i--) {
                            int tk2 = seqw[r * 12 + i];
                            int a2 = (tk2 >= 0 && tk2 < 4) ? 2 : ((tk2 >= 4 && tk2 < 8) ? 1 : 0);
                            c += a2 - 1;
                            if (!found && c == 0) {
                                ps0 = tk2;
                                ps1 = (i + 1 < TSTEPS) ? seqw[r * 12 + i + 1] : -1;
                                found = true;
                            }
                        }
                    }
                    st[5] = ps0; st[6] = ps1;
                }
            }
            __syncwarp();
        }

        // ---- finalize group: cnt + lengths ----
        if (tk == 0) {
            out[OFF_CNT + rowBase + rA] = (float)stw[rA * 8 + 0];
            out[OFF_LEN + rowBase + rA] = (float)stw[rA * 8 + 4];
            out[OFF_CNT + rowBase + rB] = (float)stw[rB * 8 + 0];
            out[OFF_LEN + rowBase + rB] = (float)stw[rB * 8 + 4];
        }
        __syncwarp();
    }
}

extern "C" void kernel_launch(void* const* d_in, const int* in_sizes, int n_in,
                              void* d_out, int out_size) {
    // inputs: [n?], input_tensor0(32), init_hidden0(128), Wx(4096), Wh(16384),
    //         b(128), Wp(2048), bp(16). 'n' scalar (size 1) may or may not be present.
    int base = (in_sizes[0] == 1) ? 1 : 0;
    const float* in0 = (const float*)d_in[base + 0];
    const float* h0  = (const float*)d_in[base + 1];
    const float* Wx  = (const float*)d_in[base + 2];
    const float* Wh  = (const float*)d_in[base + 3];
    const float* b   = (const float*)d_in[base + 4];
    const float* Wp  = (const float*)d_in[base + 5];
    const float* bp  = (const float*)d_in[base + 6];

    size_t smem = (size_t)SM_TOTF * sizeof(float);
    cudaFuncSetAttribute(eq_sampler, cudaFuncAttributeMaxDynamicSharedMemorySize, (int)smem);
    eq_sampler<<<NBLOCKS, THREADS, smem>>>(in0, h0, Wx, Wh, b, Wp, bp, (float*)d_out);
}